// round 8
// baseline (speedup 1.0000x reference)
#include <cuda_runtime.h>
#include <cuda_bf16.h>
#include <math.h>
#include <stdint.h>

#define N_NODES 20000
#define N_EDGES 200000
#define CH 64
#define HC 256
#define NHEAD 4

// ---------------- scratch ----------------
__device__ __align__(256) float    g_h[N_NODES * CH];
__device__ __align__(256) __nv_bfloat16 g_hs[N_NODES * 128];
__device__ __align__(256) __nv_bfloat16 g_fs[N_EDGES * 128];
__device__ __align__(256) __nv_bfloat16 g_es[N_EDGES * 48];
__device__ __align__(256) __nv_bfloat16 g_aggs[N_NODES * 512];   // agg split [hi256|lo256]
__device__ __align__(256) __nv_bfloat16 g_wprep[8 * 256 * 192];
__device__ __align__(256) __nv_bfloat16 g_w2p[2 * 64 * 768];     // Wnode reordered [c][k'=hi|lo|hi]
__device__ __align__(256) float    g_b2[2 * 64];
__device__ __align__(256) __nv_bfloat16 g_wce0[256 * 48];
__device__ __align__(256) float    g_bce0[256];
__device__ __align__(256) float    g_hni[N_NODES * HC];
__device__ __align__(256) float    g_hnj[N_NODES * HC];
__device__ __align__(256) float    g_score[N_EDGES * NHEAD];
// CSR by dst
__device__ __align__(256) int g_deg[N_NODES];
__device__ __align__(256) int g_off[N_NODES + 1];
__device__ __align__(256) int g_cursor[N_NODES];
__device__ __align__(256) int g_eidx[N_EDGES];

// ---------------- helpers ----------------
__device__ __forceinline__ uint32_t smem_u32(const void* p) {
    uint32_t a;
    asm("{ .reg .u64 t; cvta.to.shared.u64 t, %1; cvt.u32.u64 %0, t; }" : "=r"(a) : "l"(p));
    return a;
}
__device__ __forceinline__ float eluf(float x) { return x > 0.f ? x : expm1f(x); }
__device__ __forceinline__ float warp_sum(float v) {
#pragma unroll
    for (int o = 16; o; o >>= 1) v += __shfl_xor_sync(0xffffffffu, v, o);
    return v;
}
__device__ __forceinline__ float warp_max(float v) {
#pragma unroll
    for (int o = 16; o; o >>= 1) v = fmaxf(v, __shfl_xor_sync(0xffffffffu, v, o));
    return v;
}
__device__ __forceinline__ void ldm_x4(uint32_t* r, uint32_t addr) {
    asm volatile("ldmatrix.sync.aligned.m8n8.x4.shared.b16 {%0,%1,%2,%3}, [%4];"
                 : "=r"(r[0]), "=r"(r[1]), "=r"(r[2]), "=r"(r[3]) : "r"(addr));
}
__device__ __forceinline__ void mma_bf16(float* d, const uint32_t* a, const uint32_t* b) {
    asm volatile("mma.sync.aligned.m16n8k16.row.col.f32.bf16.bf16.f32 "
                 "{%0,%1,%2,%3}, {%4,%5,%6,%7}, {%8,%9}, {%0,%1,%2,%3};"
                 : "+f"(d[0]), "+f"(d[1]), "+f"(d[2]), "+f"(d[3])
                 : "r"(a[0]), "r"(a[1]), "r"(a[2]), "r"(a[3]), "r"(b[0]), "r"(b[1]));
}

#define MM_SMEM 153600

// ======== core mma tile (K templated; HSPLIT>0 -> A stored as [hi|lo] 2*HSPLIT wide) ========
template<int KSTEPS, int HSPLIT>
__device__ __forceinline__ void mma_tile_to_stage(
    char* smem, const __nv_bfloat16* __restrict__ A, const __nv_bfloat16* __restrict__ Wp,
    int row0, int M, int tid, int w, int lane) {
    constexpr int KELEM = KSTEPS * 16;
    constexpr int STRIDE = KELEM + 8;
    constexpr int AROW = HSPLIT ? 2 * HSPLIT : KELEM;
    constexpr int CPR = KELEM / 8;
    constexpr int TILEB = 16 * STRIDE * 2;
    __nv_bfloat16* smA = (__nv_bfloat16*)smem;
    __nv_bfloat16* smB = (__nv_bfloat16*)(smem + 128 * STRIDE * 2);

    for (int u = tid; u < 128 * CPR; u += 512) {
        int m = u / CPR, k0 = (u % CPR) * 8;
        int sc = (HSPLIT && k0 >= HSPLIT) ? k0 - HSPLIT : k0;
        int mm = row0 + m < M ? row0 + m : M - 1;
        int bytes = (row0 + m < M) ? 16 : 0;
        const void* gp = A + (size_t)mm * AROW + sc;
        uint32_t sa = smem_u32(smA + m * STRIDE + k0);
        asm volatile("cp.async.cg.shared.global [%0], [%1], 16, %2;"
                     :: "r"(sa), "l"(gp), "r"(bytes));
    }
    for (int u = tid; u < 256 * CPR; u += 512) {
        int n = u / CPR, k0 = (u % CPR) * 8;
        uint32_t sa = smem_u32(smB + n * STRIDE + k0);
        asm volatile("cp.async.cg.shared.global [%0], [%1], 16;"
                     :: "r"(sa), "l"(Wp + (size_t)n * KELEM + k0));
    }
    asm volatile("cp.async.commit_group;");
    asm volatile("cp.async.wait_group 0;" ::: "memory");
    __syncthreads();

    const int mw = (w >> 3) * 64;
    const int nw = (w & 7) * 32;
    const int g = lane >> 3, r = lane & 7;

    float acc[4][4][4];
#pragma unroll
    for (int i = 0; i < 4; i++)
#pragma unroll
        for (int j = 0; j < 4; j++)
#pragma unroll
            for (int q = 0; q < 4; q++) acc[i][j][q] = 0.f;

    uint32_t aAddr = smem_u32(smA) + ((mw + (g & 1) * 8 + r) * STRIDE + (g >> 1) * 8) * 2;
    uint32_t bAddr = smem_u32(smB) + ((nw + (g >> 1) * 8 + r) * STRIDE + (g & 1) * 8) * 2;

#pragma unroll
    for (int ks = 0; ks < KSTEPS; ks++) {
        uint32_t af[4][4], bf[2][4];
#pragma unroll
        for (int i = 0; i < 4; i++) ldm_x4(af[i], aAddr + i * TILEB);
#pragma unroll
        for (int p = 0; p < 2; p++) ldm_x4(bf[p], bAddr + p * TILEB);
#pragma unroll
        for (int i = 0; i < 4; i++)
#pragma unroll
            for (int j = 0; j < 4; j++)
                mma_bf16(acc[i][j], af[i], &bf[j >> 1][(j & 1) * 2]);
        aAddr += 32;
        bAddr += 32;
    }

    __syncthreads();
    float* stage = (float*)smem;
#pragma unroll
    for (int i = 0; i < 4; i++)
#pragma unroll
        for (int j = 0; j < 4; j++) {
            int m = mw + i * 16 + (lane >> 2);
            int n = nw + j * 8 + (lane & 3) * 2;
            stage[m * 260 + n] = acc[i][j][0];
            stage[m * 260 + n + 1] = acc[i][j][1];
            stage[(m + 8) * 260 + n] = acc[i][j][2];
            stage[(m + 8) * 260 + n + 1] = acc[i][j][3];
        }
}

// ======== node GEMMs (ni, nj) ========
__global__ void __launch_bounds__(512, 1)
gemm_node2(const __nv_bfloat16* __restrict__ A, const __nv_bfloat16* __restrict__ WpBase,
           float* __restrict__ Cni, float* __restrict__ Cnj) {
    extern __shared__ __align__(1024) char smem[];
    const int tid = threadIdx.x, w = tid >> 5, lane = tid & 31;
    const int row0 = blockIdx.x * 128;
    const __nv_bfloat16* Wp = WpBase + (size_t)blockIdx.y * (256 * 192);
    float* C = blockIdx.y ? Cnj : Cni;

    mma_tile_to_stage<12, 64>(smem, A, Wp, row0, N_NODES, tid, w, lane);
    __syncthreads();

    float* stage = (float*)smem;
    int rows = min(128, N_NODES - row0);
    for (int u = tid; u < rows * 64; u += 512) {
        int m2 = u >> 6, c4 = (u & 63) * 4;
        float4 v = *(float4*)(stage + m2 * 260 + c4);
        *(float4*)(C + (size_t)(row0 + m2) * 256 + c4) = v;
    }
}

// per-edge epilogue body (warp-collective)
__device__ __forceinline__ void edge_finish(int e, float* v, const float* sAttn, int lane) {
    float p[NHEAD];
#pragma unroll
    for (int h = 0; h < NHEAD; h++) {
        float a0 = sAttn[h * 64 + lane];
        float a1 = sAttn[h * 64 + lane + 32];
        float x0 = v[2 * h], x1 = v[2 * h + 1];
        float l0 = x0 > 0.f ? x0 : 0.01f * x0;
        float l1 = x1 > 0.f ? x1 : 0.01f * x1;
        p[h] = l0 * a0 + l1 * a1;
    }
#pragma unroll
    for (int o = 16; o; o >>= 1) {
#pragma unroll
        for (int h = 0; h < NHEAD; h++)
            p[h] += __shfl_xor_sync(0xffffffffu, p[h], o);
    }
    if (lane < NHEAD) g_score[e * NHEAD + lane] = p[lane];

    float m0 = 0.25f * (v[0] + v[2] + v[4] + v[6]);
    float m1 = 0.25f * (v[1] + v[3] + v[5] + v[7]);
    float sum = warp_sum(m0 + m1);
    float sq = warp_sum(m0 * m0 + m1 * m1);
    float mean = sum * (1.f / 64.f);
    float var = sq * (1.f / 64.f) - mean * mean;
    float rs = rsqrtf(var + 1e-5f);
    float f0 = eluf((m0 - mean) * rs);
    float f1 = eluf((m1 - mean) * rs);
    __nv_bfloat16 h0 = __float2bfloat16(f0);
    __nv_bfloat16 h1 = __float2bfloat16(f1);
    size_t b = (size_t)e * 128;
    g_fs[b + lane] = h0;
    g_fs[b + lane + 32] = h1;
    g_fs[b + 64 + lane] = __float2bfloat16(f0 - __bfloat162float(h0));
    g_fs[b + 96 + lane] = __float2bfloat16(f1 - __bfloat162float(h1));
}

// ======== fused edge GEMM + scores + next-layer f ========
template<int KSTEPS, int HSPLIT>
__global__ void __launch_bounds__(512, 1)
gemm_edge(const __nv_bfloat16* __restrict__ A, const __nv_bfloat16* __restrict__ Wp,
          const float* __restrict__ bias_e_l, const float* __restrict__ attn_l,
          const int* __restrict__ src, const int* __restrict__ dst) {
    extern __shared__ __align__(1024) char smem[];
    const int tid = threadIdx.x, w = tid >> 5, lane = tid & 31;
    const int row0 = blockIdx.x * 128;

    mma_tile_to_stage<KSTEPS, HSPLIT>(smem, A, Wp, row0, N_EDGES, tid, w, lane);

    int* sSrc = (int*)(smem + 133120);
    int* sDst = (int*)(smem + 133632);
    float* sAttn = (float*)(smem + 134144);
    float* sBias = (float*)(smem + 135168);
    if (tid < 128) {
        int e = row0 + tid;
        sSrc[tid] = (e < N_EDGES) ? src[e] : 0;
        sDst[tid] = (e < N_EDGES) ? dst[e] : 0;
    } else if (tid < 384) {
        sAttn[tid - 128] = attn_l[tid - 128];
    } else {
        int c = (tid - 384) * 2;
        sBias[c] = bias_e_l[c];
        sBias[c + 1] = bias_e_l[c + 1];
    }
    __syncthreads();

    float* stage = (float*)smem;
    for (int k = 0; k < 8; k += 2) {
        int el0 = w * 8 + k;
        int e0 = row0 + el0, e1 = e0 + 1;
        if (e0 >= N_EDGES) break;
        bool ok1 = (e1 < N_EDGES);
        int s0 = sSrc[el0], d0 = sDst[el0];
        int s1 = sSrc[el0 + 1], d1 = sDst[el0 + 1];
        const float* pni0 = g_hni + (size_t)s0 * HC;
        const float* pnj0 = g_hnj + (size_t)d0 * HC;
        const float* pni1 = g_hni + (size_t)s1 * HC;
        const float* pnj1 = g_hnj + (size_t)d1 * HC;

        float v0[8], v1[8];
#pragma unroll
        for (int j = 0; j < 8; j++) {
            int c = lane + 32 * j;
            v0[j] = stage[el0 * 260 + c] + pni0[c] + pnj0[c] + sBias[c];
            v1[j] = stage[(el0 + 1) * 260 + c] + pni1[c] + pnj1[c] + sBias[c];
        }
        edge_finish(e0, v0, sAttn, lane);
        if (ok1) edge_finish(e1, v1, sAttn, lane);
    }
}

// ======== node gather: softmax + aggregate RAW h per head -> g_aggs (split) ========
__global__ void __launch_bounds__(256)
node_gather_agg(const int* __restrict__ src) {
    int n = (blockIdx.x * blockDim.x + threadIdx.x) >> 5;
    if (n >= N_NODES) return;
    int lane = threadIdx.x & 31;
    int off0 = g_off[n], off1 = g_off[n + 1];

    float acc0[4] = {0.f, 0.f, 0.f, 0.f};   // channel lane, per head
    float acc1[4] = {0.f, 0.f, 0.f, 0.f};   // channel lane+32, per head
    if (off0 < off1) {
        float mx0 = -1e30f, mx1 = -1e30f, mx2 = -1e30f, mx3 = -1e30f;
        for (int i = off0 + lane; i < off1; i += 32) {
            int e = g_eidx[i];
            float4 s = *(const float4*)(g_score + (size_t)e * 4);
            mx0 = fmaxf(mx0, s.x); mx1 = fmaxf(mx1, s.y);
            mx2 = fmaxf(mx2, s.z); mx3 = fmaxf(mx3, s.w);
        }
        mx0 = warp_max(mx0); mx1 = warp_max(mx1);
        mx2 = warp_max(mx2); mx3 = warp_max(mx3);

        float den0 = 0.f, den1 = 0.f, den2 = 0.f, den3 = 0.f;
        for (int chunk = off0; chunk < off1; chunk += 32) {
            int i = chunk + lane;
            float wx = 0.f, wy = 0.f, wz = 0.f, ww = 0.f;
            int se = 0;
            if (i < off1) {
                int e = g_eidx[i];
                float4 s = *(const float4*)(g_score + (size_t)e * 4);
                wx = __expf(s.x - mx0); wy = __expf(s.y - mx1);
                wz = __expf(s.z - mx2); ww = __expf(s.w - mx3);
                se = src[e];
            }
            den0 += wx; den1 += wy; den2 += wz; den3 += ww;
            int cnt = min(32, off1 - chunk);
            int j = 0;
            for (; j + 3 < cnt; j += 4) {
#pragma unroll
                for (int q = 0; q < 4; q++) {
                    float bx = __shfl_sync(0xffffffffu, wx, j + q);
                    float by = __shfl_sync(0xffffffffu, wy, j + q);
                    float bz = __shfl_sync(0xffffffffu, wz, j + q);
                    float bw = __shfl_sync(0xffffffffu, ww, j + q);
                    int sj = __shfl_sync(0xffffffffu, se, j + q);
                    const float* hr = g_h + (size_t)sj * CH;
                    float t0 = hr[lane], t1 = hr[32 + lane];
                    acc0[0] += bx * t0; acc0[1] += by * t0;
                    acc0[2] += bz * t0; acc0[3] += bw * t0;
                    acc1[0] += bx * t1; acc1[1] += by * t1;
                    acc1[2] += bz * t1; acc1[3] += bw * t1;
                }
            }
            for (; j < cnt; j++) {
                float bx = __shfl_sync(0xffffffffu, wx, j);
                float by = __shfl_sync(0xffffffffu, wy, j);
                float bz = __shfl_sync(0xffffffffu, wz, j);
                float bw = __shfl_sync(0xffffffffu, ww, j);
                int sj = __shfl_sync(0xffffffffu, se, j);
                const float* hr = g_h + (size_t)sj * CH;
                float t0 = hr[lane], t1 = hr[32 + lane];
                acc0[0] += bx * t0; acc0[1] += by * t0;
                acc0[2] += bz * t0; acc0[3] += bw * t0;
                acc1[0] += bx * t1; acc1[1] += by * t1;
                acc1[2] += bz * t1; acc1[3] += bw * t1;
            }
        }
        den0 = warp_sum(den0); den1 = warp_sum(den1);
        den2 = warp_sum(den2); den3 = warp_sum(den3);
        float r0 = 1.f / den0, r1 = 1.f / den1, r2 = 1.f / den2, r3 = 1.f / den3;
        acc0[0] *= r0; acc0[1] *= r1; acc0[2] *= r2; acc0[3] *= r3;
        acc1[0] *= r0; acc1[1] *= r1; acc1[2] *= r2; acc1[3] *= r3;
    }

    size_t b = (size_t)n * 512;
#pragma unroll
    for (int h = 0; h < NHEAD; h++) {
        int p0 = h * 64 + lane;
        int p1 = h * 64 + 32 + lane;
        __nv_bfloat16 hi0 = __float2bfloat16(acc0[h]);
        __nv_bfloat16 hi1 = __float2bfloat16(acc1[h]);
        g_aggs[b + p0] = hi0;
        g_aggs[b + p1] = hi1;
        g_aggs[b + 256 + p0] = __float2bfloat16(acc0[h] - __bfloat162float(hi0));
        g_aggs[b + 256 + p1] = __float2bfloat16(acc1[h] - __bfloat162float(hi1));
    }
}

// ======== agg GEMM: h_new = instnorm(agg @ W2 + b2) -> elu -> g_h + g_hs ========
#define AG_A_OFF 99328
#define AG_SMEM  150784
__global__ void __launch_bounds__(512, 1)
gemm_agg(const __nv_bfloat16* __restrict__ W2p, const float* __restrict__ b2) {
    extern __shared__ __align__(1024) char smem[];
    __nv_bfloat16* smB = (__nv_bfloat16*)smem;                 // [64][776]
    __nv_bfloat16* smA = (__nv_bfloat16*)(smem + AG_A_OFF);    // [128][200]
    const int tid = threadIdx.x, w = tid >> 5, lane = tid & 31;
    const int row0 = blockIdx.x * 128;

    // B fill (once)
    for (int u = tid; u < 64 * 96; u += 512) {
        int n = u / 96, k0 = (u % 96) * 8;
        uint32_t sa = smem_u32(smB + n * 776 + k0);
        asm volatile("cp.async.cg.shared.global [%0], [%1], 16;"
                     :: "r"(sa), "l"(W2p + (size_t)n * 768 + k0));
    }
    asm volatile("cp.async.commit_group;");

    const int mw = (w >> 1) * 16;
    const int nw = (w & 1) * 32;
    const int g = lane >> 3, r = lane & 7;
    float acc[4][4];
#pragma unroll
    for (int j = 0; j < 4; j++)
#pragma unroll
        for (int q = 0; q < 4; q++) acc[j][q] = 0.f;

    for (int chunk = 0; chunk < 4; chunk++) {
        for (int u = tid; u < 128 * 24; u += 512) {
            int m = u / 24, kl = (u % 24) * 8;
            int kg = chunk * 192 + kl;
            int sc = kg < 256 ? kg : kg - 256;
            int mm = row0 + m < N_NODES ? row0 + m : N_NODES - 1;
            int bytes = (row0 + m < N_NODES) ? 16 : 0;
            uint32_t sa = smem_u32(smA + m * 200 + kl);
            asm volatile("cp.async.cg.shared.global [%0], [%1], 16, %2;"
                         :: "r"(sa), "l"(g_aggs + (size_t)mm * 512 + sc), "r"(bytes));
        }
        asm volatile("cp.async.commit_group;");
        asm volatile("cp.async.wait_group 0;" ::: "memory");
        __syncthreads();

        uint32_t aAddr = smem_u32(smA) + ((mw + (g & 1) * 8 + r) * 200 + (g >> 1) * 8) * 2;
        uint32_t bAddr = smem_u32(smB) + ((nw + (g >> 1) * 8 + r) * 776 + chunk * 192 + (g & 1) * 8) * 2;
#pragma unroll
        for (int ks = 0; ks < 12; ks++) {
            uint32_t af[4], bf[2][4];
            ldm_x4(af, aAddr);
#pragma unroll
            for (int p = 0; p < 2; p++) ldm_x4(bf[p], bAddr + p * (16 * 776 * 2));
#pragma unroll
            for (int j = 0; j < 4; j++)
                mma_bf16(acc[j], af, &bf[j >> 1][(j & 1) * 2]);
            aAddr += 32;
            bAddr += 32;
        }
        __syncthreads();
    }

    // stage [128][68] (aliases smA region)
    float* stage = (float*)(smem + AG_A_OFF);
#pragma unroll
    for (int j = 0; j < 4; j++) {
        int m = mw + (lane >> 2);
        int nn = nw + j * 8 + (lane & 3) * 2;
        stage[m * 68 + nn] = acc[j][0];
        stage[m * 68 + nn + 1] = acc[j][1];
        stage[(m + 8) * 68 + nn] = acc[j][2];
        stage[(m + 8) * 68 + nn + 1] = acc[j][3];
    }
    __syncthreads();

    // norm + elu + split: 16 warps x 8 rows
    for (int rr = 0; rr < 8; rr++) {
        int rl = w * 8 + rr;
        int n = row0 + rl;
        if (n >= N_NODES) break;
        float m0 = stage[rl * 68 + lane] + b2[lane];
        float m1 = stage[rl * 68 + 32 + lane] + b2[32 + lane];
        float sum = warp_sum(m0 + m1);
        float sq = warp_sum(m0 * m0 + m1 * m1);
        float mean = sum * (1.f / 64.f);
        float var = sq * (1.f / 64.f) - mean * mean;
        float rs = rsqrtf(var + 1e-5f);
        float h0 = eluf((m0 - mean) * rs);
        float h1 = eluf((m1 - mean) * rs);
        g_h[(size_t)n * CH + lane] = h0;
        g_h[(size_t)n * CH + lane + 32] = h1;
        __nv_bfloat16 b0 = __float2bfloat16(h0);
        __nv_bfloat16 b1 = __float2bfloat16(h1);
        size_t bb = (size_t)n * 128;
        g_hs[bb + lane] = b0;
        g_hs[bb + lane + 32] = b1;
        g_hs[bb + 64 + lane] = __float2bfloat16(h0 - __bfloat162float(b0));
        g_hs[bb + 96 + lane] = __float2bfloat16(h1 - __bfloat162float(b1));
    }
}

// ---------------- fp32 SGEMM (node input / final output) ----------------
__global__ void gemm64(const float* __restrict__ A, const float* __restrict__ B,
                       const float* __restrict__ bias, float* __restrict__ Cout,
                       __nv_bfloat16* __restrict__ Csplit,
                       int M, int K, int Nt) {
    __shared__ __align__(16) float sAt[65][68];
    __shared__ __align__(16) float sB[65][68];
    const int row0 = blockIdx.x * 64;
    const int col0 = blockIdx.y * 64;
    const int tid = threadIdx.x;

    for (int idx = tid; idx < 64 * K; idx += 256) {
        int r = idx / K, k = idx - r * K;
        sAt[k][r] = (row0 + r < M) ? A[(size_t)(row0 + r) * K + k] : 0.f;
    }
    for (int idx = tid; idx < K * 64; idx += 256) {
        int k = idx >> 6, c = idx & 63;
        sB[k][c] = B[(size_t)k * Nt + col0 + c];
    }
    __syncthreads();

    const int tx = tid & 15, ty = tid >> 4;
    float acc[4][4];
#pragma unroll
    for (int i = 0; i < 4; i++)
#pragma unroll
        for (int j = 0; j < 4; j++) acc[i][j] = 0.f;

#pragma unroll 4
    for (int k = 0; k < K; k++) {
        float4 a4 = *(const float4*)&sAt[k][ty * 4];
        float4 b4 = *(const float4*)&sB[k][tx * 4];
        float aa[4] = {a4.x, a4.y, a4.z, a4.w};
        float bb[4] = {b4.x, b4.y, b4.z, b4.w};
#pragma unroll
        for (int i = 0; i < 4; i++)
#pragma unroll
            for (int j = 0; j < 4; j++) acc[i][j] += aa[i] * bb[j];
    }
    float bv[4];
#pragma unroll
    for (int j = 0; j < 4; j++) bv[j] = bias ? bias[col0 + tx * 4 + j] : 0.f;
#pragma unroll
    for (int i = 0; i < 4; i++) {
        int r = row0 + ty * 4 + i;
        if (r < M) {
#pragma unroll
            for (int j = 0; j < 4; j++) {
                float val = acc[i][j] + bv[j];
                int col = col0 + tx * 4 + j;
                if (Cout) Cout[(size_t)r * Nt + col] = val;
                if (Csplit) {
                    __nv_bfloat16 hi = __float2bfloat16(val);
                    Csplit[(size_t)r * 128 + col] = hi;
                    Csplit[(size_t)r * 128 + 64 + col] = __float2bfloat16(val - __bfloat162float(hi));
                }
            }
        }
    }
}

// ---------------- weight preps ----------------
__global__ void prep_all(const float* __restrict__ Wni, const float* __restrict__ Wnj,
                         const float* __restrict__ Wfij) {
    int mat = blockIdx.x / 192;               // 0..5
    int idx = (blockIdx.x % 192) * 256 + threadIdx.x;
    int l = mat / 3, type = mat % 3;          // type 0:ni 1:nj 2:fij
    const float* W = (type == 0 ? Wni : type == 1 ? Wnj : Wfij) + (size_t)l * 64 * 256;
    int slot = l * 4 + (type == 2 ? 3 : type);
    __nv_bfloat16* Wp = g_wprep + (size_t)slot * (256 * 192);
    int n = idx / 192, kk = idx - n * 192;
    int k = kk & 63;
    float v = W[(size_t)k * 256 + n];
    __nv_bfloat16 hi = __float2bfloat16(v);
    __nv_bfloat16 out = hi;
    if (kk >= 64 && kk < 128) out = __float2bfloat16(v - __bfloat162float(hi));
    Wp[idx] = out;
}

// W2p[l][c][p] : p blocks [hi|lo|hi] of 0.25*Wnode[l][k][h*64+c], p%256 = h*64+k
__global__ void prep_w2(const float* __restrict__ Wnode, const float* __restrict__ bnode) {
    int idx = blockIdx.x * blockDim.x + threadIdx.x;
    if (idx >= 2 * 64 * 768) return;
    int l = idx / (64 * 768);
    int rem = idx % (64 * 768);
    int c = rem / 768, p = rem % 768;
    int block = p >> 8, q = p & 255;
    int h = q >> 6, k = q & 63;
    float v = 0.25f * Wnode[(size_t)l * 64 * 256 + k * 256 + h * 64 + c];
    __nv_bfloat16 hi = __float2bfloat16(v);
    g_w2p[idx] = (block == 1) ? __float2bfloat16(v - __bfloat162float(hi)) : hi;
    if (p == 0) {
        float s = 0.f;
#pragma unroll
        for (int hh = 0; hh < 4; hh++) s += bnode[(size_t)l * 256 + hh * 64 + c];
        g_b2[l * 64 + c] = 0.25f * s;
    }
}

// combined layer-0 edge weight
__global__ void prep_edge0(const float* __restrict__ We0, const float* __restrict__ be0,
                           const float* __restrict__ Wfij0, const float* __restrict__ bias_e0) {
    int n = threadIdx.x;
    float col[64];
#pragma unroll
    for (int j = 0; j < 64; j++) col[j] = Wfij0[j * 256 + n];
    float bs = bias_e0[n];
#pragma unroll
    for (int j = 0; j < 64; j++) bs += be0[j] * col[j];
    g_bce0[n] = bs;
    for (int k = 0; k < 15; k++) {
        float s = 0.f;
#pragma unroll
        for (int j = 0; j < 64; j++) s += We0[k * 64 + j] * col[j];
        __nv_bfloat16 hi = __float2bfloat16(s);
        __nv_bfloat16 lo = __float2bfloat16(s - __bfloat162float(hi));
        g_wce0[n * 48 + k] = hi;
        g_wce0[n * 48 + 15 + k] = lo;
        g_wce0[n * 48 + 30 + k] = hi;
    }
    for (int c = 45; c < 48; c++) g_wce0[n * 48 + c] = __float2bfloat16(0.f);
}

__global__ void split_efeat(const float* __restrict__ efeat) {
    int idx = blockIdx.x * blockDim.x + threadIdx.x;
    if (idx >= N_EDGES * 48) return;
    int e = idx / 48, c = idx - e * 48;
    __nv_bfloat16 out = __float2bfloat16(0.f);
    if (c < 45) {
        int k = c < 15 ? c : (c < 30 ? c - 15 : c - 30);
        float v = efeat[e * 15 + k];
        __nv_bfloat16 hi = __float2bfloat16(v);
        out = (c < 30) ? hi : __float2bfloat16(v - __bfloat162float(hi));
    }
    g_es[idx] = out;
}

// ---------------- CSR build ----------------
__global__ void csr_zero() {
    int i = blockIdx.x * blockDim.x + threadIdx.x;
    if (i < N_NODES) g_deg[i] = 0;
}
__global__ void csr_hist(const int* __restrict__ dst) {
    int e = blockIdx.x * blockDim.x + threadIdx.x;
    if (e < N_EDGES) atomicAdd(&g_deg[dst[e]], 1);
}
__global__ void __launch_bounds__(1024) csr_scan() {
    __shared__ int ssum[1024];
    int t = threadIdx.x;
    int base = t * 20;
    int s = 0;
    int loc[20];
#pragma unroll
    for (int j = 0; j < 20; j++) {
        int idx = base + j;
        loc[j] = s;
        if (idx < N_NODES) s += g_deg[idx];
    }
    ssum[t] = s;
    __syncthreads();
    for (int o = 1; o < 1024; o <<= 1) {
        int v = (t >= o) ? ssum[t - o] : 0;
        __syncthreads();
        ssum[t] += v;
        __syncthreads();
    }
    int pre = (t == 0) ? 0 : ssum[t - 1];
#pragma unroll
    for (int j = 0; j < 20; j++) {
        int idx = base + j;
        if (idx < N_NODES) {
            int o = pre + loc[j];
            g_off[idx] = o;
            g_cursor[idx] = o;
        }
    }
    if (t == 1023) g_off[N_NODES] = ssum[1023];
}
__global__ void csr_scatter(const int* __restrict__ dst) {
    int e = blockIdx.x * blockDim.x + threadIdx.x;
    if (e >= N_EDGES) return;
    int pos = atomicAdd(&g_cursor[dst[e]], 1);
    g_eidx[pos] = e;
}

// ---------------- launcher ----------------
extern "C" void kernel_launch(void* const* d_in, const int* in_sizes, int n_in,
                              void* d_out, int out_size) {
    const float* x = (const float*)d_in[0];
    const float* efeat = (const float*)d_in[1];
    const int* src = (const int*)d_in[2];
    const int* dst = (const int*)d_in[3];
    const float* Wn0 = (const float*)d_in[4];
    const float* bn0 = (const float*)d_in[5];
    const float* We0 = (const float*)d_in[6];
    const float* be0 = (const float*)d_in[7];
    const float* Wnode = (const float*)d_in[8];
    const float* bnode = (const float*)d_in[9];
    const float* Wni = (const float*)d_in[10];
    const float* Wnj = (const float*)d_in[11];
    const float* Wfij = (const float*)d_in[12];
    const float* attn = (const float*)d_in[13];
    const float* bias_e = (const float*)d_in[14];
    const float* Wf = (const float*)d_in[15];
    const float* bf = (const float*)d_in[16];

    float *ph, *phni, *phnj, *pbce0, *pb2;
    __nv_bfloat16 *phs, *pfs, *pwp, *pes, *pwce0, *pw2p;
    cudaGetSymbolAddress((void**)&ph, g_h);
    cudaGetSymbolAddress((void**)&phni, g_hni);
    cudaGetSymbolAddress((void**)&phnj, g_hnj);
    cudaGetSymbolAddress((void**)&phs, g_hs);
    cudaGetSymbolAddress((void**)&pfs, g_fs);
    cudaGetSymbolAddress((void**)&pwp, g_wprep);
    cudaGetSymbolAddress((void**)&pes, g_es);
    cudaGetSymbolAddress((void**)&pwce0, g_wce0);
    cudaGetSymbolAddress((void**)&pbce0, g_bce0);
    cudaGetSymbolAddress((void**)&pw2p, g_w2p);
    cudaGetSymbolAddress((void**)&pb2, g_b2);

    cudaFuncSetAttribute(gemm_node2, cudaFuncAttributeMaxDynamicSharedMemorySize, MM_SMEM);
    cudaFuncSetAttribute(gemm_edge<3, 0>, cudaFuncAttributeMaxDynamicSharedMemorySize, MM_SMEM);
    cudaFuncSetAttribute(gemm_edge<12, 64>, cudaFuncAttributeMaxDynamicSharedMemorySize, MM_SMEM);
    cudaFuncSetAttribute(gemm_agg, cudaFuncAttributeMaxDynamicSharedMemorySize, AG_SMEM);

    const dim3 blk(256);
    const int NB_N = (N_NODES + 63) / 64;
    const int TB_N = (N_NODES + 127) / 128;   // 157
    const int TB_E = (N_EDGES + 127) / 128;   // 1563
    const int WPSZ = 256 * 192;

    // CSR build
    csr_zero<<<(N_NODES + 255) / 256, blk>>>();
    csr_hist<<<(N_EDGES + 255) / 256, blk>>>(dst);
    csr_scan<<<1, 1024>>>();
    csr_scatter<<<(N_EDGES + 255) / 256, blk>>>(dst);

    // preps
    prep_all<<<6 * 192, blk>>>(Wni, Wnj, Wfij);
    prep_w2<<<(2 * 64 * 768 + 255) / 256, blk>>>(Wnode, bnode);
    prep_edge0<<<1, 256>>>(We0, be0, Wfij, bias_e);
    split_efeat<<<(N_EDGES * 48 + 255) / 256, blk>>>(efeat);

    // node input projection (fp32 h + split bf16)
    gemm64<<<dim3(NB_N, 1), blk>>>(x, Wn0, bn0, ph, phs, N_NODES, 65, 64);

    // ---- layer 0 ----
    gemm_node2<<<dim3(TB_N, 2), 512, MM_SMEM>>>(phs, pwp, phni, phnj);
    gemm_edge<3, 0><<<TB_E, 512, MM_SMEM>>>(pes, pwce0, pbce0, attn, src, dst);
    node_gather_agg<<<(N_NODES * 32 + 255) / 256, blk>>>(src);
    gemm_agg<<<TB_N, 512, AG_SMEM>>>(pw2p, pb2);

    // ---- layer 1 ----
    gemm_node2<<<dim3(TB_N, 2), 512, MM_SMEM>>>(phs, pwp + (size_t)4 * WPSZ, phni, phnj);
    gemm_edge<12, 64><<<TB_E, 512, MM_SMEM>>>(pfs, pwp + (size_t)7 * WPSZ,
                                              bias_e + 256, attn + 256, src, dst);
    node_gather_agg<<<(N_NODES * 32 + 255) / 256, blk>>>(src);
    gemm_agg<<<TB_N, 512, AG_SMEM>>>(pw2p + (size_t)64 * 768, pb2 + 64);

    gemm64<<<dim3(NB_N, 1), blk>>>(ph, Wf, bf, (float*)d_out, nullptr, N_NODES, 64, 64);
}

// round 9
// speedup vs baseline: 1.0697x; 1.0697x over previous
#include <cuda_runtime.h>
#include <cuda_bf16.h>
#include <math.h>
#include <stdint.h>

#define N_NODES 20000
#define N_EDGES 200000
#define CH 64
#define HC 256
#define NHEAD 4
#define NTILES 1563

// ---------------- scratch ----------------
__device__ __align__(256) float    g_h[N_NODES * CH];
__device__ __align__(256) __nv_bfloat16 g_hs[N_NODES * 128];
__device__ __align__(256) __nv_bfloat16 g_fs[N_EDGES * 128];
__device__ __align__(256) __nv_bfloat16 g_es[N_EDGES * 48];
__device__ __align__(256) __nv_bfloat16 g_wprep[8 * 256 * 192];
__device__ __align__(256) __nv_bfloat16 g_wce0[256 * 48];
__device__ __align__(256) float    g_bce0[256];
__device__ __align__(256) float    g_hni[N_NODES * HC];
__device__ __align__(256) float    g_hnj[N_NODES * HC];
__device__ __align__(256) float    g_hproj[N_NODES * HC];
__device__ __align__(256) float    g_score[N_EDGES * NHEAD];
__device__ __align__(256) int g_deg[N_NODES];
__device__ __align__(256) int g_off[N_NODES + 1];
__device__ __align__(256) int g_cursor[N_NODES];
__device__ __align__(256) int g_eidx[N_EDGES];

// ---------------- helpers ----------------
__device__ __forceinline__ uint32_t smem_u32(const void* p) {
    uint32_t a;
    asm("{ .reg .u64 t; cvta.to.shared.u64 t, %1; cvt.u32.u64 %0, t; }" : "=r"(a) : "l"(p));
    return a;
}
__device__ __forceinline__ float eluf(float x) { return x > 0.f ? x : expm1f(x); }
__device__ __forceinline__ float warp_sum(float v) {
#pragma unroll
    for (int o = 16; o; o >>= 1) v += __shfl_xor_sync(0xffffffffu, v, o);
    return v;
}
__device__ __forceinline__ float warp_max(float v) {
#pragma unroll
    for (int o = 16; o; o >>= 1) v = fmaxf(v, __shfl_xor_sync(0xffffffffu, v, o));
    return v;
}
__device__ __forceinline__ void ldm_x4(uint32_t* r, uint32_t addr) {
    asm volatile("ldmatrix.sync.aligned.m8n8.x4.shared.b16 {%0,%1,%2,%3}, [%4];"
                 : "=r"(r[0]), "=r"(r[1]), "=r"(r[2]), "=r"(r[3]) : "r"(addr));
}
__device__ __forceinline__ void mma_bf16(float* d, const uint32_t* a, const uint32_t* b) {
    asm volatile("mma.sync.aligned.m16n8k16.row.col.f32.bf16.bf16.f32 "
                 "{%0,%1,%2,%3}, {%4,%5,%6,%7}, {%8,%9}, {%0,%1,%2,%3};"
                 : "+f"(d[0]), "+f"(d[1]), "+f"(d[2]), "+f"(d[3])
                 : "r"(a[0]), "r"(a[1]), "r"(a[2]), "r"(a[3]), "r"(b[0]), "r"(b[1]));
}

#define MM_SMEM 153600

// ======== non-persistent mma tile (node GEMMs): fill, mma, stage [128][260] ========
template<int KSTEPS, int HSPLIT>
__device__ __forceinline__ void mma_tile_to_stage(
    char* smem, const __nv_bfloat16* __restrict__ A, const __nv_bfloat16* __restrict__ Wp,
    int row0, int M, int tid, int w, int lane) {
    constexpr int KELEM = KSTEPS * 16;
    constexpr int STRIDE = KELEM + 8;
    constexpr int AROW = HSPLIT ? 2 * HSPLIT : KELEM;
    constexpr int CPR = KELEM / 8;
    constexpr int TILEB = 16 * STRIDE * 2;
    __nv_bfloat16* smA = (__nv_bfloat16*)smem;
    __nv_bfloat16* smB = (__nv_bfloat16*)(smem + 128 * STRIDE * 2);

    for (int u = tid; u < 128 * CPR; u += 512) {
        int m = u / CPR, k0 = (u % CPR) * 8;
        int sc = (HSPLIT && k0 >= HSPLIT) ? k0 - HSPLIT : k0;
        int mm = row0 + m < M ? row0 + m : M - 1;
        int bytes = (row0 + m < M) ? 16 : 0;
        uint32_t sa = smem_u32(smA + m * STRIDE + k0);
        asm volatile("cp.async.cg.shared.global [%0], [%1], 16, %2;"
                     :: "r"(sa), "l"(A + (size_t)mm * AROW + sc), "r"(bytes));
    }
    for (int u = tid; u < 256 * CPR; u += 512) {
        int n = u / CPR, k0 = (u % CPR) * 8;
        uint32_t sa = smem_u32(smB + n * STRIDE + k0);
        asm volatile("cp.async.cg.shared.global [%0], [%1], 16;"
                     :: "r"(sa), "l"(Wp + (size_t)n * KELEM + k0));
    }
    asm volatile("cp.async.commit_group;");
    asm volatile("cp.async.wait_group 0;" ::: "memory");
    __syncthreads();

    const int mw = (w >> 3) * 64;
    const int nw = (w & 7) * 32;
    const int g = lane >> 3, r = lane & 7;

    float acc[4][4][4];
#pragma unroll
    for (int i = 0; i < 4; i++)
#pragma unroll
        for (int j = 0; j < 4; j++)
#pragma unroll
            for (int q = 0; q < 4; q++) acc[i][j][q] = 0.f;

    uint32_t aAddr = smem_u32(smA) + ((mw + (g & 1) * 8 + r) * STRIDE + (g >> 1) * 8) * 2;
    uint32_t bAddr = smem_u32(smB) + ((nw + (g >> 1) * 8 + r) * STRIDE + (g & 1) * 8) * 2;

#pragma unroll
    for (int ks = 0; ks < KSTEPS; ks++) {
        uint32_t af[4][4], bf[2][4];
#pragma unroll
        for (int i = 0; i < 4; i++) ldm_x4(af[i], aAddr + i * TILEB);
#pragma unroll
        for (int p = 0; p < 2; p++) ldm_x4(bf[p], bAddr + p * TILEB);
#pragma unroll
        for (int i = 0; i < 4; i++)
#pragma unroll
            for (int j = 0; j < 4; j++)
                mma_bf16(acc[i][j], af[i], &bf[j >> 1][(j & 1) * 2]);
        aAddr += 32;
        bAddr += 32;
    }

    __syncthreads();
    float* stage = (float*)smem;
#pragma unroll
    for (int i = 0; i < 4; i++)
#pragma unroll
        for (int j = 0; j < 4; j++) {
            int m = mw + i * 16 + (lane >> 2);
            int n = nw + j * 8 + (lane & 3) * 2;
            stage[m * 260 + n] = acc[i][j][0];
            stage[m * 260 + n + 1] = acc[i][j][1];
            stage[(m + 8) * 260 + n] = acc[i][j][2];
            stage[(m + 8) * 260 + n + 1] = acc[i][j][3];
        }
}

// ======== node GEMMs: ni, nj, node(hproj)+bias ========
__global__ void __launch_bounds__(512, 1)
gemm_node3(const __nv_bfloat16* __restrict__ A, const __nv_bfloat16* __restrict__ WpBase,
           const float* __restrict__ bnode_l,
           float* __restrict__ Cni, float* __restrict__ Cnj, float* __restrict__ Cnode) {
    extern __shared__ __align__(1024) char smem[];
    const int tid = threadIdx.x, w = tid >> 5, lane = tid & 31;
    const int row0 = blockIdx.x * 128;
    const int y = blockIdx.y;
    const __nv_bfloat16* Wp = WpBase + (size_t)y * (256 * 192);
    float* C = (y == 0) ? Cni : (y == 1) ? Cnj : Cnode;
    const float* bias = (y == 2) ? bnode_l : nullptr;

    mma_tile_to_stage<12, 64>(smem, A, Wp, row0, N_NODES, tid, w, lane);
    __syncthreads();

    float* stage = (float*)smem;
    int rows = min(128, N_NODES - row0);
    for (int u = tid; u < rows * 64; u += 512) {
        int m2 = u >> 6, c4 = (u & 63) * 4;
        float4 v = *(float4*)(stage + m2 * 260 + c4);
        if (bias) {
            float4 bb = *(const float4*)(bias + c4);
            v.x += bb.x; v.y += bb.y; v.z += bb.z; v.w += bb.w;
        }
        *(float4*)(C + (size_t)(row0 + m2) * 256 + c4) = v;
    }
}

// per-edge epilogue body (warp-collective)
__device__ __forceinline__ void edge_finish(int e, float* v, const float* sAttn, int lane, int writeF) {
    float p[NHEAD];
#pragma unroll
    for (int h = 0; h < NHEAD; h++) {
        float a0 = sAttn[h * 64 + lane];
        float a1 = sAttn[h * 64 + lane + 32];
        float x0 = v[2 * h], x1 = v[2 * h + 1];
        float l0 = x0 > 0.f ? x0 : 0.01f * x0;
        float l1 = x1 > 0.f ? x1 : 0.01f * x1;
        p[h] = l0 * a0 + l1 * a1;
    }
#pragma unroll
    for (int o = 16; o; o >>= 1) {
#pragma unroll
        for (int h = 0; h < NHEAD; h++)
            p[h] += __shfl_xor_sync(0xffffffffu, p[h], o);
    }
    if (lane < NHEAD) g_score[e * NHEAD + lane] = p[lane];

    if (writeF) {
        float m0 = 0.25f * (v[0] + v[2] + v[4] + v[6]);
        float m1 = 0.25f * (v[1] + v[3] + v[5] + v[7]);
        float sum = warp_sum(m0 + m1);
        float sq = warp_sum(m0 * m0 + m1 * m1);
        float mean = sum * (1.f / 64.f);
        float var = sq * (1.f / 64.f) - mean * mean;
        float rs = rsqrtf(var + 1e-5f);
        float f0 = eluf((m0 - mean) * rs);
        float f1 = eluf((m1 - mean) * rs);
        __nv_bfloat16 h0 = __float2bfloat16(f0);
        __nv_bfloat16 h1 = __float2bfloat16(f1);
        size_t b = (size_t)e * 128;
        g_fs[b + lane] = h0;
        g_fs[b + lane + 32] = h1;
        g_fs[b + 64 + lane] = __float2bfloat16(f0 - __bfloat162float(h0));
        g_fs[b + 96 + lane] = __float2bfloat16(f1 - __bfloat162float(h1));
    }
}

// ======== PERSISTENT fused edge GEMM: B resident, A prefetch overlaps epilogue ========
template<int KSTEPS, int HSPLIT>
__global__ void __launch_bounds__(512)
gemm_edge_p(const __nv_bfloat16* __restrict__ A, const __nv_bfloat16* __restrict__ Wp,
            const float* __restrict__ bias_e_l, const float* __restrict__ attn_l,
            const int* __restrict__ src, const int* __restrict__ dst,
            int numTiles, int writeF) {
    constexpr int KELEM = KSTEPS * 16;
    constexpr int STRIDE = KELEM + 8;
    constexpr int AROW = HSPLIT ? 2 * HSPLIT : KELEM;
    constexpr int CPR = KELEM / 8;
    constexpr int TILEB = 16 * STRIDE * 2;
    constexpr int OFF_A = 256 * STRIDE * 2;
    constexpr int OFF_STAGE = OFF_A + 128 * STRIDE * 2;
    constexpr int OFF_SRC = OFF_STAGE + 64 * 260 * 4;
    constexpr int OFF_DST = OFF_SRC + 2 * 128 * 4;
    constexpr int OFF_ATTN = OFF_DST + 2 * 128 * 4;
    constexpr int OFF_BIAS = OFF_ATTN + 1024;
    extern __shared__ __align__(1024) char smem[];
    __nv_bfloat16* smB = (__nv_bfloat16*)smem;
    __nv_bfloat16* smA = (__nv_bfloat16*)(smem + OFF_A);
    float* stage = (float*)(smem + OFF_STAGE);
    int* sSrc = (int*)(smem + OFF_SRC);
    int* sDst = (int*)(smem + OFF_DST);
    float* sAttn = (float*)(smem + OFF_ATTN);
    float* sBias = (float*)(smem + OFF_BIAS);
    const int tid = threadIdx.x, w = tid >> 5, lane = tid & 31;

    // prologue: B (persistent), attn, bias
    for (int u = tid; u < 256 * CPR; u += 512) {
        int n = u / CPR, k0 = (u % CPR) * 8;
        uint32_t sa = smem_u32(smB + n * STRIDE + k0);
        asm volatile("cp.async.cg.shared.global [%0], [%1], 16;"
                     :: "r"(sa), "l"(Wp + (size_t)n * KELEM + k0));
    }
    if (tid < 256) sAttn[tid] = attn_l[tid];
    else sBias[tid - 256] = bias_e_l[tid - 256];
    asm volatile("cp.async.commit_group;");

    auto fillA = [&](int t, int par) {
        int row0 = t * 128;
        for (int u = tid; u < 128 * CPR; u += 512) {
            int m = u / CPR, k0 = (u % CPR) * 8;
            int sc = (HSPLIT && k0 >= HSPLIT) ? k0 - HSPLIT : k0;
            int mm = row0 + m < N_EDGES ? row0 + m : N_EDGES - 1;
            int bytes = (row0 + m < N_EDGES) ? 16 : 0;
            uint32_t sa = smem_u32(smA + m * STRIDE + k0);
            asm volatile("cp.async.cg.shared.global [%0], [%1], 16, %2;"
                         :: "r"(sa), "l"(A + (size_t)mm * AROW + sc), "r"(bytes));
        }
        if (tid < 64) {
            int c = tid & 31;
            int isd = tid >> 5;
            const int* gp = isd ? dst : src;
            int eo = row0 + c * 4;
            int bytes = (eo + 4 <= N_EDGES) ? 16 : 0;
            int eoc = eo + 4 <= N_EDGES ? eo : 0;
            uint32_t sa = smem_u32((isd ? sDst : sSrc) + par * 128 + c * 4);
            asm volatile("cp.async.ca.shared.global [%0], [%1], 16, %2;"
                         :: "r"(sa), "l"(gp + eoc), "r"(bytes));
        }
        asm volatile("cp.async.commit_group;");
    };

    int t = blockIdx.x;
    int par = 0;
    if (t < numTiles) fillA(t, par);

    const int nw = (w & 7) * 32;
    const int g = lane >> 3, r = lane & 7;
    const int mw = (w >> 3) * 64;

    for (; t < numTiles; t += gridDim.x) {
        asm volatile("cp.async.wait_group 0;" ::: "memory");
        __syncthreads();

        float acc[4][4][4];
#pragma unroll
        for (int i = 0; i < 4; i++)
#pragma unroll
            for (int j = 0; j < 4; j++)
#pragma unroll
                for (int q = 0; q < 4; q++) acc[i][j][q] = 0.f;

        uint32_t aAddr = smem_u32(smA) + ((mw + (g & 1) * 8 + r) * STRIDE + (g >> 1) * 8) * 2;
        uint32_t bAddr = smem_u32(smB) + ((nw + (g >> 1) * 8 + r) * STRIDE + (g & 1) * 8) * 2;
#pragma unroll
        for (int ks = 0; ks < KSTEPS; ks++) {
            uint32_t af[4][4], bf[2][4];
#pragma unroll
            for (int i = 0; i < 4; i++) ldm_x4(af[i], aAddr + i * TILEB);
#pragma unroll
            for (int p = 0; p < 2; p++) ldm_x4(bf[p], bAddr + p * TILEB);
#pragma unroll
            for (int i = 0; i < 4; i++)
#pragma unroll
                for (int j = 0; j < 4; j++)
                    mma_bf16(acc[i][j], af[i], &bf[j >> 1][(j & 1) * 2]);
            aAddr += 32;
            bAddr += 32;
        }
        __syncthreads();   // all warps done with smA

        int nxt = t + gridDim.x;
        if (nxt < numTiles) fillA(nxt, par ^ 1);   // overlaps stage+epilogue

        int row0 = t * 128;
#pragma unroll
        for (int hh = 0; hh < 2; hh++) {
            if ((w >> 3) == hh) {
#pragma unroll
                for (int i = 0; i < 4; i++)
#pragma unroll
                    for (int j = 0; j < 4; j++) {
                        int m = i * 16 + (lane >> 2);
                        int n = nw + j * 8 + (lane & 3) * 2;
                        stage[m * 260 + n] = acc[i][j][0];
                        stage[m * 260 + n + 1] = acc[i][j][1];
                        stage[(m + 8) * 260 + n] = acc[i][j][2];
                        stage[(m + 8) * 260 + n + 1] = acc[i][j][3];
                    }
            }
            __syncthreads();

            for (int k = 0; k < 4; k += 2) {
                int eloc = w * 4 + k;
                int el = hh * 64 + eloc;
                int e0 = row0 + el, e1 = e0 + 1;
                if (e0 >= N_EDGES) continue;
                bool ok1 = (e1 < N_EDGES);
                int s0 = sSrc[par * 128 + el], d0 = sDst[par * 128 + el];
                int s1 = sSrc[par * 128 + el + 1], d1 = sDst[par * 128 + el + 1];
                const float* pni0 = g_hni + (size_t)s0 * HC;
                const float* pnj0 = g_hnj + (size_t)d0 * HC;
                const float* pni1 = g_hni + (size_t)s1 * HC;
                const float* pnj1 = g_hnj + (size_t)d1 * HC;
                float v0[8], v1[8];
#pragma unroll
                for (int j = 0; j < 8; j++) {
                    int c = lane + 32 * j;
                    v0[j] = stage[eloc * 260 + c] + pni0[c] + pnj0[c] + sBias[c];
                    v1[j] = stage[(eloc + 1) * 260 + c] + pni1[c] + pnj1[c] + sBias[c];
                }
                edge_finish(e0, v0, sAttn, lane, writeF);
                if (ok1) edge_finish(e1, v1, sAttn, lane, writeF);
            }
            __syncthreads();
        }
        par ^= 1;
    }
}

// ======== node gather: softmax + aggregate hproj + instnorm + elu (warp/node) ========
__global__ void __launch_bounds__(256)
node_gather(const int* __restrict__ src) {
    int n = (blockIdx.x * blockDim.x + threadIdx.x) >> 5;
    if (n >= N_NODES) return;
    int lane = threadIdx.x & 31;
    int off0 = g_off[n], off1 = g_off[n + 1];

    float h0 = 0.f, h1 = 0.f;
    if (off0 < off1) {
        float mx0 = -1e30f, mx1 = -1e30f, mx2 = -1e30f, mx3 = -1e30f;
        for (int i = off0 + lane; i < off1; i += 32) {
            int e = g_eidx[i];
            float4 s = *(const float4*)(g_score + (size_t)e * 4);
            mx0 = fmaxf(mx0, s.x); mx1 = fmaxf(mx1, s.y);
            mx2 = fmaxf(mx2, s.z); mx3 = fmaxf(mx3, s.w);
        }
        mx0 = warp_max(mx0); mx1 = warp_max(mx1);
        mx2 = warp_max(mx2); mx3 = warp_max(mx3);

        float den0 = 0.f, den1 = 0.f, den2 = 0.f, den3 = 0.f;
        float a0h[4] = {0.f, 0.f, 0.f, 0.f};
        float a1h[4] = {0.f, 0.f, 0.f, 0.f};
        for (int chunk = off0; chunk < off1; chunk += 32) {
            int i = chunk + lane;
            float wx = 0.f, wy = 0.f, wz = 0.f, ww = 0.f;
            int se = 0;
            if (i < off1) {
                int e = g_eidx[i];
                float4 s = *(const float4*)(g_score + (size_t)e * 4);
                wx = __expf(s.x - mx0); wy = __expf(s.y - mx1);
                wz = __expf(s.z - mx2); ww = __expf(s.w - mx3);
                se = src[e];
            }
            den0 += wx; den1 += wy; den2 += wz; den3 += ww;
            int cnt = min(32, off1 - chunk);
            int j = 0;
            for (; j + 1 < cnt; j += 2) {
                float bx0 = __shfl_sync(0xffffffffu, wx, j);
                float by0 = __shfl_sync(0xffffffffu, wy, j);
                float bz0 = __shfl_sync(0xffffffffu, wz, j);
                float bw0 = __shfl_sync(0xffffffffu, ww, j);
                int sj0 = __shfl_sync(0xffffffffu, se, j);
                float bx1 = __shfl_sync(0xffffffffu, wx, j + 1);
                float by1 = __shfl_sync(0xffffffffu, wy, j + 1);
                float bz1 = __shfl_sync(0xffffffffu, wz, j + 1);
                float bw1 = __shfl_sync(0xffffffffu, ww, j + 1);
                int sj1 = __shfl_sync(0xffffffffu, se, j + 1);
                const float* hp0 = g_hproj + (size_t)sj0 * HC;
                const float* hp1 = g_hproj + (size_t)sj1 * HC;
                a0h[0] += hp0[lane] * bx0 + hp1[lane] * bx1;
                a0h[1] += hp0[64 + lane] * by0 + hp1[64 + lane] * by1;
                a0h[2] += hp0[128 + lane] * bz0 + hp1[128 + lane] * bz1;
                a0h[3] += hp0[192 + lane] * bw0 + hp1[192 + lane] * bw1;
                a1h[0] += hp0[32 + lane] * bx0 + hp1[32 + lane] * bx1;
                a1h[1] += hp0[96 + lane] * by0 + hp1[96 + lane] * by1;
                a1h[2] += hp0[160 + lane] * bz0 + hp1[160 + lane] * bz1;
                a1h[3] += hp0[224 + lane] * bw0 + hp1[224 + lane] * bw1;
            }
            if (j < cnt) {
                float bx = __shfl_sync(0xffffffffu, wx, j);
                float by = __shfl_sync(0xffffffffu, wy, j);
                float bz = __shfl_sync(0xffffffffu, wz, j);
                float bw = __shfl_sync(0xffffffffu, ww, j);
                int sj = __shfl_sync(0xffffffffu, se, j);
                const float* hp = g_hproj + (size_t)sj * HC;
                a0h[0] += hp[lane] * bx;
                a0h[1] += hp[64 + lane] * by;
                a0h[2] += hp[128 + lane] * bz;
                a0h[3] += hp[192 + lane] * bw;
                a1h[0] += hp[32 + lane] * bx;
                a1h[1] += hp[96 + lane] * by;
                a1h[2] += hp[160 + lane] * bz;
                a1h[3] += hp[224 + lane] * bw;
            }
        }
        den0 = warp_sum(den0); den1 = warp_sum(den1);
        den2 = warp_sum(den2); den3 = warp_sum(den3);
        float r0 = 1.f / den0, r1 = 1.f / den1, r2 = 1.f / den2, r3 = 1.f / den3;
        float m0 = 0.25f * (a0h[0] * r0 + a0h[1] * r1 + a0h[2] * r2 + a0h[3] * r3);
        float m1 = 0.25f * (a1h[0] * r0 + a1h[1] * r1 + a1h[2] * r2 + a1h[3] * r3);

        float sum = warp_sum(m0 + m1);
        float sq = warp_sum(m0 * m0 + m1 * m1);
        float mean = sum * (1.f / 64.f);
        float var = sq * (1.f / 64.f) - mean * mean;
        float rs = rsqrtf(var + 1e-5f);
        h0 = eluf((m0 - mean) * rs);
        h1 = eluf((m1 - mean) * rs);
    }

    g_h[(size_t)n * CH + lane] = h0;
    g_h[(size_t)n * CH + lane + 32] = h1;
    __nv_bfloat16 b0 = __float2bfloat16(h0);
    __nv_bfloat16 b1 = __float2bfloat16(h1);
    size_t b = (size_t)n * 128;
    g_hs[b + lane] = b0;
    g_hs[b + lane + 32] = b1;
    g_hs[b + 64 + lane] = __float2bfloat16(h0 - __bfloat162float(b0));
    g_hs[b + 96 + lane] = __float2bfloat16(h1 - __bfloat162float(b1));
}

// ---------------- fp32 SGEMM (node input / final output) ----------------
__global__ void gemm64(const float* __restrict__ A, const float* __restrict__ B,
                       const float* __restrict__ bias, float* __restrict__ Cout,
                       __nv_bfloat16* __restrict__ Csplit,
                       int M, int K, int Nt) {
    __shared__ __align__(16) float sAt[65][68];
    __shared__ __align__(16) float sB[65][68];
    const int row0 = blockIdx.x * 64;
    const int col0 = blockIdx.y * 64;
    const int tid = threadIdx.x;

    for (int idx = tid; idx < 64 * K; idx += 256) {
        int r = idx / K, k = idx - r * K;
        sAt[k][r] = (row0 + r < M) ? A[(size_t)(row0 + r) * K + k] : 0.f;
    }
    for (int idx = tid; idx < K * 64; idx += 256) {
        int k = idx >> 6, c = idx & 63;
        sB[k][c] = B[(size_t)k * Nt + col0 + c];
    }
    __syncthreads();

    const int tx = tid & 15, ty = tid >> 4;
    float acc[4][4];
#pragma unroll
    for (int i = 0; i < 4; i++)
#pragma unroll
        for (int j = 0; j < 4; j++) acc[i][j] = 0.f;

#pragma unroll 4
    for (int k = 0; k < K; k++) {
        float4 a4 = *(const float4*)&sAt[k][ty * 4];
        float4 b4 = *(const float4*)&sB[k][tx * 4];
        float aa[4] = {a4.x, a4.y, a4.z, a4.w};
        float bb[4] = {b4.x, b4.y, b4.z, b4.w};
#pragma unroll
        for (int i = 0; i < 4; i++)
#pragma unroll
            for (int j = 0; j < 4; j++) acc[i][j] += aa[i] * bb[j];
    }
    float bv[4];
#pragma unroll
    for (int j = 0; j < 4; j++) bv[j] = bias ? bias[col0 + tx * 4 + j] : 0.f;
#pragma unroll
    for (int i = 0; i < 4; i++) {
        int r = row0 + ty * 4 + i;
        if (r < M) {
#pragma unroll
            for (int j = 0; j < 4; j++) {
                float val = acc[i][j] + bv[j];
                int col = col0 + tx * 4 + j;
                if (Cout) Cout[(size_t)r * Nt + col] = val;
                if (Csplit) {
                    __nv_bfloat16 hi = __float2bfloat16(val);
                    Csplit[(size_t)r * 128 + col] = hi;
                    Csplit[(size_t)r * 128 + 64 + col] = __float2bfloat16(val - __bfloat162float(hi));
                }
            }
        }
    }
}

// ---------------- merged preps: wprep(8) + edge0 combine + efeat split ----------------
__global__ void prep_misc(const float* __restrict__ Wni, const float* __restrict__ Wnj,
                          const float* __restrict__ Wnode, const float* __restrict__ Wfij,
                          const float* __restrict__ We0, const float* __restrict__ be0,
                          const float* __restrict__ bias_e, const float* __restrict__ efeat) {
    int b = blockIdx.x;
    int tid = threadIdx.x;
    if (b < 1536) {
        int mat = b / 192;
        int idx = (b % 192) * 256 + tid;
        int l = mat >> 2, type = mat & 3;
        const float* W = (type == 0 ? Wni : type == 1 ? Wnj : type == 2 ? Wnode : Wfij)
                         + (size_t)l * 64 * 256;
        __nv_bfloat16* Wp = g_wprep + (size_t)mat * (256 * 192);
        int n = idx / 192, kk = idx - n * 192;
        int k = kk & 63;
        float v = W[(size_t)k * 256 + n];
        __nv_bfloat16 hi = __float2bfloat16(v);
        __nv_bfloat16 out = hi;
        if (kk >= 64 && kk < 128) out = __float2bfloat16(v - __bfloat162float(hi));
        Wp[idx] = out;
    } else if (b == 1536) {
        int n = tid;
        float col[64];
#pragma unroll
        for (int j = 0; j < 64; j++) col[j] = Wfij[j * 256 + n];
        float bs = bias_e[n];
#pragma unroll
        for (int j = 0; j < 64; j++) bs += be0[j] * col[j];
        g_bce0[n] = bs;
        for (int k = 0; k < 15; k++) {
            float s = 0.f;
#pragma unroll
            for (int j = 0; j < 64; j++) s += We0[k * 64 + j] * col[j];
            __nv_bfloat16 hi = __float2bfloat16(s);
            __nv_bfloat16 lo = __float2bfloat16(s - __bfloat162float(hi));
            g_wce0[n * 48 + k] = hi;
            g_wce0[n * 48 + 15 + k] = lo;
            g_wce0[n * 48 + 30 + k] = hi;
        }
        for (int c = 45; c < 48; c++) g_wce0[n * 48 + c] = __float2bfloat16(0.f);
    } else {
        int idx = (b - 1537) * 256 + tid;
        if (idx >= N_EDGES * 48) return;
        int e = idx / 48, c = idx - e * 48;
        __nv_bfloat16 out = __float2bfloat16(0.f);
        if (c < 45) {
            int k = c < 15 ? c : (c < 30 ? c - 15 : c - 30);
            float v = efeat[e * 15 + k];
            __nv_bfloat16 hi = __float2bfloat16(v);
            out = (c < 30) ? hi : __float2bfloat16(v - __bfloat162float(hi));
        }
        g_es[idx] = out;
    }
}

// ---------------- CSR build ----------------
__global__ void csr_zero() {
    int i = blockIdx.x * blockDim.x + threadIdx.x;
    if (i < N_NODES) g_deg[i] = 0;
}
__global__ void csr_hist(const int* __restrict__ dst) {
    int e = blockIdx.x * blockDim.x + threadIdx.x;
    if (e < N_EDGES) atomicAdd(&g_deg[dst[e]], 1);
}
__global__ void __launch_bounds__(1024) csr_scan() {
    __shared__ int ssum[1024];
    int t = threadIdx.x;
    int base = t * 20;
    int s = 0;
    int loc[20];
#pragma unroll
    for (int j = 0; j < 20; j++) {
        int idx = base + j;
        loc[j] = s;
        if (idx < N_NODES) s += g_deg[idx];
    }
    ssum[t] = s;
    __syncthreads();
    for (int o = 1; o < 1024; o <<= 1) {
        int v = (t >= o) ? ssum[t - o] : 0;
        __syncthreads();
        ssum[t] += v;
        __syncthreads();
    }
    int pre = (t == 0) ? 0 : ssum[t - 1];
#pragma unroll
    for (int j = 0; j < 20; j++) {
        int idx = base + j;
        if (idx < N_NODES) {
            int o = pre + loc[j];
            g_off[idx] = o;
            g_cursor[idx] = o;
        }
    }
    if (t == 1023) g_off[N_NODES] = ssum[1023];
}
__global__ void csr_scatter(const int* __restrict__ dst) {
    int e = blockIdx.x * blockDim.x + threadIdx.x;
    if (e >= N_EDGES) return;
    int pos = atomicAdd(&g_cursor[dst[e]], 1);
    g_eidx[pos] = e;
}

// ---------------- launcher ----------------
extern "C" void kernel_launch(void* const* d_in, const int* in_sizes, int n_in,
                              void* d_out, int out_size) {
    const float* x = (const float*)d_in[0];
    const float* efeat = (const float*)d_in[1];
    const int* src = (const int*)d_in[2];
    const int* dst = (const int*)d_in[3];
    const float* Wn0 = (const float*)d_in[4];
    const float* bn0 = (const float*)d_in[5];
    const float* We0 = (const float*)d_in[6];
    const float* be0 = (const float*)d_in[7];
    const float* Wnode = (const float*)d_in[8];
    const float* bnode = (const float*)d_in[9];
    const float* Wni = (const float*)d_in[10];
    const float* Wnj = (const float*)d_in[11];
    const float* Wfij = (const float*)d_in[12];
    const float* attn = (const float*)d_in[13];
    const float* bias_e = (const float*)d_in[14];
    const float* Wf = (const float*)d_in[15];
    const float* bf = (const float*)d_in[16];

    float *ph, *phni, *phnj, *phproj, *pbce0;
    __nv_bfloat16 *phs, *pfs, *pwp, *pes, *pwce0;
    cudaGetSymbolAddress((void**)&ph, g_h);
    cudaGetSymbolAddress((void**)&phni, g_hni);
    cudaGetSymbolAddress((void**)&phnj, g_hnj);
    cudaGetSymbolAddress((void**)&phproj, g_hproj);
    cudaGetSymbolAddress((void**)&phs, g_hs);
    cudaGetSymbolAddress((void**)&pfs, g_fs);
    cudaGetSymbolAddress((void**)&pwp, g_wprep);
    cudaGetSymbolAddress((void**)&pes, g_es);
    cudaGetSymbolAddress((void**)&pwce0, g_wce0);
    cudaGetSymbolAddress((void**)&pbce0, g_bce0);

    cudaFuncSetAttribute(gemm_node3, cudaFuncAttributeMaxDynamicSharedMemorySize, MM_SMEM);
    cudaFuncSetAttribute(gemm_edge_p<3, 0>, cudaFuncAttributeMaxDynamicSharedMemorySize, 113664);
    cudaFuncSetAttribute(gemm_edge_p<12, 64>, cudaFuncAttributeMaxDynamicSharedMemorySize, 224256);

    const dim3 blk(256);
    const int NB_N = (N_NODES + 63) / 64;     // 313
    const int TB_N = (N_NODES + 127) / 128;   // 157
    const int WPSZ = 256 * 192;

    // 0: node input projection
    gemm64<<<dim3(NB_N, 1), blk>>>(x, Wn0, bn0, ph, phs, N_NODES, 65, 64);
    // 1: all preps in one launch
    prep_misc<<<1537 + (N_EDGES * 48) / 256, blk>>>(Wni, Wnj, Wnode, Wfij, We0, be0, bias_e, efeat);
    // 2: layer-0 node GEMMs
    gemm_node3<<<dim3(TB_N, 3), 512, MM_SMEM>>>(phs, pwp, bnode, phni, phnj, phproj);
    // 3: layer-0 edge GEMM (persistent)  <- ncu capture target
    gemm_edge_p<3, 0><<<148, 512, 113664>>>(pes, pwce0, pbce0, attn, src, dst, NTILES, 1);
    // 4-7: CSR build (needed before node_gather)
    csr_zero<<<(N_NODES + 255) / 256, blk>>>();
    csr_hist<<<(N_EDGES + 255) / 256, blk>>>(dst);
    csr_scan<<<1, 1024>>>();
    csr_scatter<<<(N_EDGES + 255) / 256, blk>>>(dst);
    // 8: layer-0 aggregate
    node_gather<<<(N_NODES * 32 + 255) / 256, blk>>>(src);
    // 9-11: layer 1
    gemm_node3<<<dim3(TB_N, 3), 512, MM_SMEM>>>(phs, pwp + (size_t)4 * WPSZ,
                                                bnode + 256, phni, phnj, phproj);
    gemm_edge_p<12, 64><<<148, 512, 224256>>>(pfs, pwp + (size_t)7 * WPSZ,
                                              bias_e + 256, attn + 256, src, dst, NTILES, 0);
    node_gather<<<(N_NODES * 32 + 255) / 256, blk>>>(src);
    // 12: output projection
    gemm64<<<dim3(NB_N, 1), blk>>>(ph, Wf, bf, (float*)d_out, nullptr, N_NODES, 64, 64);
}